// round 4
// baseline (speedup 1.0000x reference)
#include <cuda_runtime.h>
#include <cstdint>

// Problem constants (fixed by setup_inputs)
#define C_    32
#define S_    9
#define H_    192
#define W_    256
#define G_    8
#define NSRC  8            // N-1 source images
#define TW    16           // pixels (w) per block tile
#define THREADS 128

#define WS    (W_*S_)      // 2304
#define HWS   (H_*WS)      // 442368
#define CHWS  (C_*HWS)     // 14155776
#define ROW   (TW*S_)      // 144 data floats per channel per tile
#define ROWP  148          // padded smem row stride (bank-conflict-free)
#define F4ROW (ROW/4)      // 36 float4 of data per channel row

// tiles: ref + 3 src ring buffers, each 32*148 floats
#define TILEP (C_*ROWP)                // 4736
#define OFF_REF   0
#define OFF_SRC0  (TILEP)              // 4736
#define OFF_SRC1  (2*TILEP)            // 9472
#define OFF_SRC2  (3*TILEP)            // 14208
// prologue scratch overlays src2 (staged only after prologue finishes)
#define OFF_WPT   OFF_SRC2             // 1024 floats: WpT[c*32+d]
#define OFF_BP    (OFF_WPT+1024)
#define OFF_PC4   (OFF_BP+32)          // 512: pc4[d*16+w]
#define OFF_U     (OFF_PC4+512)        // 512: u[c*16+w]
#define OFF_ATT   (OFF_U+512)          // 144: att[w*9+s]
#define SMEM_FLOATS (4*TILEP)          // 18944
#define SMEM_BYTES  (SMEM_FLOATS*4)    // 75776 -> 3 blocks/SM

__device__ __forceinline__ void cp16(float* dst, const float4* src) {
    uint32_t s = (uint32_t)__cvta_generic_to_shared(dst);
    asm volatile("cp.async.cg.shared.global [%0], [%1], 16;\n" :: "r"(s), "l"(src));
}
__device__ __forceinline__ void cp_commit() { asm volatile("cp.async.commit_group;\n" ::); }
__device__ __forceinline__ void cp_wait2()  { asm volatile("cp.async.wait_group 2;\n" ::); }
__device__ __forceinline__ void cp_wait1()  { asm volatile("cp.async.wait_group 1;\n" ::); }
__device__ __forceinline__ void cp_wait0()  { asm volatile("cp.async.wait_group 0;\n" ::); }

// Each warp stages ITS OWN 8-channel slice: 8 ch * 36 f4 = 288 f4, 9 per lane.
__device__ __forceinline__ void stage_slice(float* dst, const float4* gbase,
                                            int wid, int lane) {
    #pragma unroll
    for (int i = 0; i < 9; i++) {
        int j  = lane + i * 32;          // 0..287 within slice
        int cl = j / F4ROW;              // local channel 0..7
        int k  = j - cl * F4ROW;         // f4 within row, 0..35
        int c  = wid * 8 + cl;           // absolute channel
        cp16(dst + c * ROWP + k * 4, gbase + (size_t)c * (HWS >> 2) + k);
    }
    cp_commit();
}

__global__ __launch_bounds__(THREADS)
void gcfs_kernel(const float* __restrict__ f,
                 const float* __restrict__ Wp,
                 const float* __restrict__ bp,
                 float* __restrict__ out) {
    extern __shared__ float sm[];
    float* refS = sm + OFF_REF;
    float* WpT  = sm + OFF_WPT;
    float* bpS  = sm + OFF_BP;
    float* pc4  = sm + OFF_PC4;
    float* uS   = sm + OFF_U;
    float* attS = sm + OFF_ATT;

    const int t    = threadIdx.x;
    const int lane = t & 31;
    const int wid  = t >> 5;
    const int h    = blockIdx.y;
    const int w0   = blockIdx.x * TW;

    const float4* fb4 = (const float4*)f;
    const size_t tile4 = ((size_t)h * WS + (size_t)w0 * S_) >> 2;

    // --- prologue staging (per-warp slices): ref, src0, src1 ---
    stage_slice(refS,          fb4 + tile4,                          wid, lane);
    stage_slice(sm + OFF_SRC0, fb4 + (size_t)1*(CHWS>>2) + tile4,    wid, lane);
    stage_slice(sm + OFF_SRC1, fb4 + (size_t)2*(CHWS>>2) + tile4,    wid, lane);

    // Wp transposed + bp (tiny, L2-resident) into scratch (src2 overlay)
    for (int i = t; i < C_ * C_; i += THREADS) {
        int d = i >> 5, c = i & 31;
        WpT[c * 32 + d] = Wp[i];
    }
    if (t < C_) bpS[t] = bp[t];

    cp_wait2();          // own ref slice done; src0/src1 still streaming
    __syncthreads();     // full ref visible to all

    // --- pc4[d][w] = sum_c Wp[d,c]*ref[c,w,4] + bp[d]  (512 items) ---
    #pragma unroll
    for (int i = 0; i < 4; i++) {
        int item = t + i * THREADS;
        int w = item & 15, d = item >> 4;
        float acc = bpS[d];
        #pragma unroll
        for (int c = 0; c < C_; c++)
            acc += WpT[c * 32 + d] * refS[c * ROWP + w * S_ + 4];
        pc4[d * 16 + w] = acc;
    }
    __syncthreads();

    // --- u[c][w] = sum_d pc4[d][w]*Wp[d,c] ---
    #pragma unroll
    for (int i = 0; i < 4; i++) {
        int item = t + i * THREADS;
        int w = item & 15, c = item >> 4;
        float acc = 0.f;
        #pragma unroll
        for (int d = 0; d < C_; d++)
            acc += pc4[d * 16 + w] * WpT[c * 32 + d];
        uS[c * 16 + w] = acc;
    }
    __syncthreads();

    // --- logits + softmax (16 lanes; one pixel per lane) ---
    if (t < TW) {
        const int w = t;
        float v = 0.f;
        #pragma unroll
        for (int d = 0; d < C_; d++) v += pc4[d * 16 + w] * bpS[d];

        float lg[S_];
        #pragma unroll
        for (int s = 0; s < S_; s++) {
            float a = v;
            #pragma unroll
            for (int c = 0; c < C_; c++)
                a += uS[c * 16 + w] * refS[c * ROWP + w * S_ + s];
            lg[s] = a * 0.17677669529663687f;   // 1/sqrt(32)
        }
        float mx = lg[0];
        #pragma unroll
        for (int s = 1; s < S_; s++) mx = fmaxf(mx, lg[s]);
        float sum = 0.f;
        #pragma unroll
        for (int s = 0; s < S_; s++) { lg[s] = expf(lg[s] - mx); sum += lg[s]; }
        float inv = 1.f / sum;
        #pragma unroll
        for (int s = 0; s < S_; s++) attS[w * S_ + s] = lg[s] * inv;
    }
    __syncthreads();

    // --- hoist ref*att into registers: thread (g,w) owns 4 channels x 9 shifts ---
    const int w = t & 15;
    const int g = t >> 4;
    float rw[4][S_];
    #pragma unroll
    for (int c = 0; c < 4; c++) {
        #pragma unroll
        for (int s = 0; s < S_; s++)
            rw[c][s] = refS[(g * 4 + c) * ROWP + w * S_ + s] * attS[w * S_ + s];
    }
    __syncthreads();     // all warps done with scratch before src2 overwrites it

    // stage src2 into the (former) scratch region — group 4
    stage_slice(sm + OFF_SRC2, fb4 + (size_t)3*(CHWS>>2) + tile4, wid, lane);

    // --- warp-autonomous main loop: NO block barriers ---
    float* const bufs[3] = { sm + OFF_SRC0, sm + OFF_SRC1, sm + OFF_SRC2 };
    const size_t outBase = (size_t)h * W_ + w0 + w;

    #pragma unroll 1
    for (int n = 0; n < NSRC; n++) {
        if (n <= 5) cp_wait2();          // src n's slice complete (2 pending)
        else if (n == 6) cp_wait1();
        else cp_wait0();

        const float* sb = bufs[n % 3];
        float acc = 0.f;
        #pragma unroll
        for (int c = 0; c < 4; c++) {
            #pragma unroll
            for (int s = 0; s < S_; s++)
                acc += rw[c][s] * sb[(g * 4 + c) * ROWP + w * S_ + s];
        }
        out[((size_t)(n * G_ + g)) * (H_ * W_) + outBase] = acc;

        // refill own slice of the buffer just consumed (same warp: safe
        // program-order reuse; cp.async data lands >>100cyc after LDS retire)
        if (n <= 4)
            stage_slice(bufs[n % 3], fb4 + (size_t)(n + 4)*(CHWS>>2) + tile4,
                        wid, lane);
    }
}

extern "C" void kernel_launch(void* const* d_in, const int* in_sizes, int n_in,
                              void* d_out, int out_size) {
    const float* f  = (const float*)d_in[0];
    const float* Wp = (const float*)d_in[1];
    const float* bp = (const float*)d_in[2];
    float* out = (float*)d_out;

    cudaFuncSetAttribute(gcfs_kernel,
                         cudaFuncAttributeMaxDynamicSharedMemorySize, SMEM_BYTES);
    dim3 grid(W_ / TW, H_);
    gcfs_kernel<<<grid, THREADS, SMEM_BYTES>>>(f, Wp, bp, out);
}